// round 2
// baseline (speedup 1.0000x reference)
#include <cuda_runtime.h>

#define D_MODEL 768
#define NH 12
#define DK 64
#define BATCH 2
#define SEQ 2048
#define MROWS (BATCH * SEQ)        // 4096
#define QKV_ELEMS (BATCH * NH * SEQ * DK)  // 3,145,728

// Scratch (allocation-free): Q/K/V in [B,H,S,dk], ctx in [B,S,D]
__device__ float g_q[QKV_ELEMS];
__device__ float g_k[QKV_ELEMS];
__device__ float g_v[QKV_ELEMS];
__device__ float g_ctx[MROWS * D_MODEL];

// ---------------------------------------------------------------------------
// Tiled GEMM: C[M=4096, N=768] = A[M,768] @ W[768,768] + bias
// BM=128, BN=128, BK=8, 256 threads, 8x8 microtile.
// HEADSPLIT=true writes C into [B, H, S, dk] layout instead of [M, N].
// ---------------------------------------------------------------------------
#define BM 128
#define BN 128
#define BK 8

template <bool HEADSPLIT>
__global__ __launch_bounds__(256) void gemm_bias_kernel(
    const float* __restrict__ A, const float* __restrict__ W,
    const float* __restrict__ bias, float* __restrict__ C)
{
    __shared__ float As[BK][BM];   // A stored transposed (k-major)
    __shared__ float Bs[BK][BN];

    const int tid = threadIdx.x;
    const int m0 = blockIdx.y * BM;
    const int n0 = blockIdx.x * BN;
    const int tx = tid & 15;   // 0..15
    const int ty = tid >> 4;   // 0..15

    // A tile load: 128 rows x 8 cols = 256 float4 (2 per row)
    const int a_row = tid >> 1;
    const int a_q   = (tid & 1) * 4;
    // B tile load: 8 rows x 128 cols = 256 float4
    const int b_row = tid >> 5;
    const int b_col = (tid & 31) * 4;

    float acc[8][8];
#pragma unroll
    for (int i = 0; i < 8; i++)
#pragma unroll
        for (int j = 0; j < 8; j++) acc[i][j] = 0.f;

    for (int k0 = 0; k0 < D_MODEL; k0 += BK) {
        float4 av = *(const float4*)&A[(size_t)(m0 + a_row) * D_MODEL + k0 + a_q];
        float4 bv = *(const float4*)&W[(size_t)(k0 + b_row) * D_MODEL + n0 + b_col];
        __syncthreads();
        As[a_q + 0][a_row] = av.x;
        As[a_q + 1][a_row] = av.y;
        As[a_q + 2][a_row] = av.z;
        As[a_q + 3][a_row] = av.w;
        *(float4*)&Bs[b_row][b_col] = bv;
        __syncthreads();
#pragma unroll
        for (int kk = 0; kk < BK; kk++) {
            float4 a0 = *(const float4*)&As[kk][ty * 8];
            float4 a1 = *(const float4*)&As[kk][ty * 8 + 4];
            float4 b0 = *(const float4*)&Bs[kk][tx * 8];
            float4 b1 = *(const float4*)&Bs[kk][tx * 8 + 4];
            float a[8] = {a0.x, a0.y, a0.z, a0.w, a1.x, a1.y, a1.z, a1.w};
            float b[8] = {b0.x, b0.y, b0.z, b0.w, b1.x, b1.y, b1.z, b1.w};
#pragma unroll
            for (int i = 0; i < 8; i++)
#pragma unroll
                for (int j = 0; j < 8; j++)
                    acc[i][j] += a[i] * b[j];
        }
    }

    // Epilogue
#pragma unroll
    for (int i = 0; i < 8; i++) {
        const int m = m0 + ty * 8 + i;
        const int bb = m / SEQ;
        const int s  = m % SEQ;
#pragma unroll
        for (int j = 0; j < 8; j++) {
            const int n = n0 + tx * 8 + j;
            float v = acc[i][j] + bias[n];
            if (HEADSPLIT) {
                const int h = n >> 6;       // n / 64
                const int d = n & 63;
                C[((size_t)(bb * NH + h) * SEQ + s) * DK + d] = v;
            } else {
                C[(size_t)m * D_MODEL + n] = v;
            }
        }
    }
}

// ---------------------------------------------------------------------------
// Flash attention (causal), fp32. One thread per query row.
// 128-query tiles, 32-key tiles staged in smem, online softmax.
// Q/K/V layout: [B, H, S, dk]; output written into g_ctx [B, S, D].
// ---------------------------------------------------------------------------
#define TQ 128
#define TK 32

__global__ __launch_bounds__(128) void attn_kernel(
    const float* __restrict__ Q, const float* __restrict__ K,
    const float* __restrict__ V, float* __restrict__ ctx)
{
    __shared__ float Ksh[TK][DK];
    __shared__ float Vsh[TK][DK];

    const int tid = threadIdx.x;
    const int q0  = blockIdx.x * TQ;
    const int bh  = blockIdx.y;          // 0..23
    const int b   = bh / NH;
    const int h   = bh % NH;
    const int qi  = q0 + tid;            // this thread's query index

    const float* Qbh = Q + (size_t)bh * SEQ * DK;
    const float* Kbh = K + (size_t)bh * SEQ * DK;
    const float* Vbh = V + (size_t)bh * SEQ * DK;

    // Load this thread's query row into registers (16 float4 = 64 floats)
    float4 q[16];
    {
        const float4* qrow = (const float4*)(Qbh + (size_t)qi * DK);
#pragma unroll
        for (int d = 0; d < 16; d++) q[d] = qrow[d];
    }

    float4 o[16];
#pragma unroll
    for (int d = 0; d < 16; d++) o[d] = make_float4(0.f, 0.f, 0.f, 0.f);
    float mval = -1e30f;
    float lval = 0.f;

    const int nkt = (q0 + TQ + TK - 1) / TK;   // causal: only tiles up to diag
    for (int kt = 0; kt < nkt; kt++) {
        const int kbase = kt * TK;

        // Cooperative tile load: tile is contiguous TK*DK floats = 512 float4
        {
            const float4* kg = (const float4*)(Kbh + (size_t)kbase * DK);
            const float4* vg = (const float4*)(Vbh + (size_t)kbase * DK);
            float4* ks = (float4*)Ksh;
            float4* vs = (float4*)Vsh;
#pragma unroll
            for (int r = 0; r < 4; r++) {
                const int f = tid + 128 * r;
                ks[f] = kg[f];
                vs[f] = vg[f];
            }
        }
        __syncthreads();

        if (kbase <= qi) {   // warp-uniform skip of fully-masked tiles
            float s[TK];
            float mnew = mval;
#pragma unroll
            for (int j = 0; j < TK; j++) {
                const float4* k4 = (const float4*)Ksh[j];
                float acc = 0.f;
#pragma unroll
                for (int d = 0; d < 16; d++) {
                    float4 kv = k4[d];
                    acc += q[d].x * kv.x;
                    acc += q[d].y * kv.y;
                    acc += q[d].z * kv.z;
                    acc += q[d].w * kv.w;
                }
                acc *= 0.125f;   // 1/sqrt(64)
                s[j] = (kbase + j <= qi) ? acc : -1e30f;
                mnew = fmaxf(mnew, s[j]);
            }
            const float corr = __expf(mval - mnew);
            mval = mnew;
            lval *= corr;
#pragma unroll
            for (int d = 0; d < 16; d++) {
                o[d].x *= corr; o[d].y *= corr;
                o[d].z *= corr; o[d].w *= corr;
            }
#pragma unroll
            for (int j = 0; j < TK; j++) {
                const float p = __expf(s[j] - mval);
                lval += p;
                const float4* v4 = (const float4*)Vsh[j];
#pragma unroll
                for (int d = 0; d < 16; d++) {
                    float4 vv = v4[d];
                    o[d].x += p * vv.x;
                    o[d].y += p * vv.y;
                    o[d].z += p * vv.z;
                    o[d].w += p * vv.w;
                }
            }
        }
        __syncthreads();
    }

    const float inv = 1.f / lval;
    float4* out = (float4*)(ctx + ((size_t)(b * SEQ + qi) * D_MODEL + h * DK));
#pragma unroll
    for (int d = 0; d < 16; d++) {
        float4 ov = o[d];
        ov.x *= inv; ov.y *= inv; ov.z *= inv; ov.w *= inv;
        out[d] = ov;
    }
}

// ---------------------------------------------------------------------------
// Launch
// ---------------------------------------------------------------------------
extern "C" void kernel_launch(void* const* d_in, const int* in_sizes, int n_in,
                              void* d_out, int out_size)
{
    const float* x  = (const float*)d_in[0];
    // d_in[1] is the causal mask (int32 tril) — causality is hardcoded.
    const float* wq = (const float*)d_in[2];
    const float* bq = (const float*)d_in[3];
    const float* wk = (const float*)d_in[4];
    const float* bk = (const float*)d_in[5];
    const float* wv = (const float*)d_in[6];
    const float* bv = (const float*)d_in[7];
    const float* wo = (const float*)d_in[8];
    const float* bo = (const float*)d_in[9];
    float* out = (float*)d_out;

    float *q_ptr, *k_ptr, *v_ptr, *ctx_ptr;
    cudaGetSymbolAddress((void**)&q_ptr,   g_q);
    cudaGetSymbolAddress((void**)&k_ptr,   g_k);
    cudaGetSymbolAddress((void**)&v_ptr,   g_v);
    cudaGetSymbolAddress((void**)&ctx_ptr, g_ctx);

    const dim3 gemm_grid(D_MODEL / BN, MROWS / BM);   // (6, 32)
    const dim3 gemm_blk(256);

    // QKV projections (head-split epilogue)
    gemm_bias_kernel<true><<<gemm_grid, gemm_blk>>>(x, wq, bq, q_ptr);
    gemm_bias_kernel<true><<<gemm_grid, gemm_blk>>>(x, wk, bk, k_ptr);
    gemm_bias_kernel<true><<<gemm_grid, gemm_blk>>>(x, wv, bv, v_ptr);

    // Causal flash attention -> ctx [B, S, D]
    const dim3 attn_grid(SEQ / TQ, BATCH * NH);       // (16, 24)
    attn_kernel<<<attn_grid, 128>>>(q_ptr, k_ptr, v_ptr, ctx_ptr);

    // Output projection
    gemm_bias_kernel<false><<<gemm_grid, gemm_blk>>>(ctx_ptr, wo, bo, out);
}